// round 1
// baseline (speedup 1.0000x reference)
#include <cuda_runtime.h>
#include <math.h>

#define NN 8192
#define DD 512
#define TEMP_INV 5.0f

// Scratch (device globals: no allocation allowed in kernel_launch)
__device__ float  g_zn[(size_t)NN * DD];         // 16 MB normalized rows
__device__ float  g_sim[(size_t)NN * NN];        // 256 MB Gram matrix
__device__ float  g_mu[NN];                      // mean of dist per index
__device__ float  g_A[NN];                       // 1/(2*var) per index
__device__ double g_neg;
__device__ double g_pos;

// ---------------------------------------------------------------------------
__global__ void init_kernel() { g_neg = 0.0; g_pos = 0.0; }

// ---------------------------------------------------------------------------
// Row normalize: one warp per row (D=512 -> 128 float4, 4 per lane)
__global__ void normalize_kernel(const float* __restrict__ z) {
    int warp = (blockIdx.x * blockDim.x + threadIdx.x) >> 5;
    int lane = threadIdx.x & 31;
    if (warp >= NN) return;
    const float4* zr = (const float4*)(z + (size_t)warp * DD);
    float4 v[4];
    float ss = 0.f;
#pragma unroll
    for (int t = 0; t < 4; t++) {
        v[t] = zr[lane + 32 * t];
        ss += v[t].x * v[t].x + v[t].y * v[t].y + v[t].z * v[t].z + v[t].w * v[t].w;
    }
#pragma unroll
    for (int o = 16; o > 0; o >>= 1) ss += __shfl_xor_sync(0xffffffffu, ss, o);
    float nrm = fmaxf(sqrtf(ss), 1e-12f);
    float inv = 1.0f / nrm;
    float4* outp = (float4*)(g_zn + (size_t)warp * DD);
#pragma unroll
    for (int t = 0; t < 4; t++) {
        float4 o4 = make_float4(v[t].x * inv, v[t].y * inv, v[t].z * inv, v[t].w * inv);
        outp[lane + 32 * t] = o4;
    }
}

// ---------------------------------------------------------------------------
// SGEMM: sim = zn * zn^T, symmetric -> compute upper-triangular 128x128 tiles,
// mirror-write the transpose. BM=BN=128, BK=16, 256 threads, 8x8 per thread.
#define BM 128
#define BN 128
#define BK 16
#define LDS_STRIDE 130   // 130 mod 32 == 2: conflict-free staging stores

__global__ void __launch_bounds__(256, 2) gemm_kernel() {
    int bc = blockIdx.x, br = blockIdx.y;
    if (br > bc) return;  // symmetry: upper triangle only

    __shared__ float As[BK][LDS_STRIDE];
    __shared__ float Bs[BK][LDS_STRIDE];

    int tid = threadIdx.x;
    int tx = tid & 15;       // 0..15 -> column group
    int ty = tid >> 4;       // 0..15 -> row group
    int row_l = tid >> 2;    // 0..63  (loader row)
    int quad  = tid & 3;     // 0..3   (loader float4 within 16-float k-slab)

    const float4* Z = (const float4*)g_zn;
    const int D4 = DD / 4;

    float acc[8][8];
#pragma unroll
    for (int i = 0; i < 8; i++)
#pragma unroll
        for (int j = 0; j < 8; j++) acc[i][j] = 0.f;

    for (int kk = 0; kk < DD; kk += BK) {
        int kq = (kk >> 2) + quad;
#pragma unroll
        for (int h = 0; h < 2; h++) {
            int m = row_l + 64 * h;
            float4 va = Z[(size_t)(br * BM + m) * D4 + kq];
            As[quad * 4 + 0][m] = va.x;
            As[quad * 4 + 1][m] = va.y;
            As[quad * 4 + 2][m] = va.z;
            As[quad * 4 + 3][m] = va.w;
            float4 vb = Z[(size_t)(bc * BN + m) * D4 + kq];
            Bs[quad * 4 + 0][m] = vb.x;
            Bs[quad * 4 + 1][m] = vb.y;
            Bs[quad * 4 + 2][m] = vb.z;
            Bs[quad * 4 + 3][m] = vb.w;
        }
        __syncthreads();

#pragma unroll
        for (int k = 0; k < BK; k++) {
            float a[8], b[8];
#pragma unroll
            for (int i = 0; i < 8; i++) a[i] = As[k][ty * 8 + i];
#pragma unroll
            for (int j = 0; j < 8; j++) b[j] = Bs[k][tx * 8 + j];
#pragma unroll
            for (int i = 0; i < 8; i++)
#pragma unroll
                for (int j = 0; j < 8; j++) acc[i][j] = fmaf(a[i], b[j], acc[i][j]);
        }
        __syncthreads();
    }

    int R = br * BM + ty * 8;
    int C = bc * BN + tx * 8;
#pragma unroll
    for (int i = 0; i < 8; i++) {
        float4* p = (float4*)(g_sim + (size_t)(R + i) * NN + C);
        p[0] = make_float4(acc[i][0], acc[i][1], acc[i][2], acc[i][3]);
        p[1] = make_float4(acc[i][4], acc[i][5], acc[i][6], acc[i][7]);
    }
    if (br != bc) {
#pragma unroll
        for (int j = 0; j < 8; j++) {
            float4* p = (float4*)(g_sim + (size_t)(C + j) * NN + R);
            p[0] = make_float4(acc[0][j], acc[1][j], acc[2][j], acc[3][j]);
            p[1] = make_float4(acc[4][j], acc[5][j], acc[6][j], acc[7][j]);
        }
    }
}

// ---------------------------------------------------------------------------
// Per-row mean/var of dist = 1 - sim (double accumulation kills the
// catastrophic cancellation in var = (sum_sq - N*mean^2)/(N-1)).
__global__ void stats_kernel() {
    int i = blockIdx.x;
    const float4* row = (const float4*)(g_sim + (size_t)i * NN);
    double s = 0.0, s2 = 0.0;
    for (int j = threadIdx.x; j < NN / 4; j += 256) {
        float4 v = row[j];
        s  += (double)v.x + (double)v.y + (double)v.z + (double)v.w;
        s2 += (double)v.x * v.x + (double)v.y * v.y + (double)v.z * v.z + (double)v.w * v.w;
    }
    __shared__ double sh[256];
    __shared__ double sh2[256];
    int t = threadIdx.x;
    sh[t] = s; sh2[t] = s2;
    __syncthreads();
    for (int st = 128; st > 0; st >>= 1) {
        if (t < st) { sh[t] += sh[t + st]; sh2[t] += sh2[t + st]; }
        __syncthreads();
    }
    if (t == 0) {
        double smean = sh[0] / (double)NN;
        double var = (sh2[0] - (double)NN * smean * smean) / (double)(NN - 1);
        g_mu[i] = (float)(1.0 - smean);           // mean of dist
        g_A[i]  = (float)(1.0 / (2.0 * var));     // 1/(2*std^2), unbiased
    }
}

// ---------------------------------------------------------------------------
// Negative sum: term = exp(sim/T + (dist - mu_j)^2 * A_j) over (i!=j, labels differ).
// Note: reference broadcasts mu/std along axis 1 (column index j); dist is
// symmetric so per-column stats == per-row stats, but we index by j exactly.
__global__ void neg_kernel(const int* __restrict__ labels) {
    int i = blockIdx.x;
    int li = labels[i];
    const float* row = g_sim + (size_t)i * NN;
    double acc = 0.0;
    for (int j = threadIdx.x; j < NN; j += 256) {
        int lj = labels[j];
        if (lj == li) continue;  // also excludes j==i automatically
        float s = row[j];
        float d = 1.0f - s;
        float tt = d - g_mu[j];
        float e = fmaf(tt * tt, g_A[j], s * TEMP_INV);
        acc += (double)expf(e);
    }
    __shared__ double sh[256];
    int t = threadIdx.x;
    sh[t] = acc;
    __syncthreads();
    for (int st = 128; st > 0; st >>= 1) {
        if (t < st) sh[t] += sh[t + st];
        __syncthreads();
    }
    if (t == 0) atomicAdd(&g_neg, sh[0]);
}

// ---------------------------------------------------------------------------
// Positive pairs: exp(sim[i, i+b]/T) where labels match, i in [0, b)
__global__ void pos_kernel(const int* __restrict__ labels) {
    int i = blockIdx.x * blockDim.x + threadIdx.x;
    double v = 0.0;
    const int b = NN / 2;
    if (i < b && labels[i] == labels[i + b]) {
        float s = g_sim[(size_t)i * NN + (i + b)];
        v = (double)expf(s * TEMP_INV);
    }
    __shared__ double sh[256];
    int t = threadIdx.x;
    sh[t] = v;
    __syncthreads();
    for (int st = 128; st > 0; st >>= 1) {
        if (t < st) sh[t] += sh[t + st];
        __syncthreads();
    }
    if (t == 0) atomicAdd(&g_pos, sh[0]);
}

// ---------------------------------------------------------------------------
__global__ void finalize_kernel(float* out) {
    out[0] = (float)(-log(g_pos / (g_pos + g_neg)));
}

// ---------------------------------------------------------------------------
extern "C" void kernel_launch(void* const* d_in, const int* in_sizes, int n_in,
                              void* d_out, int out_size) {
    const float* z      = (const float*)d_in[0];
    const int*   labels = (const int*)d_in[1];
    float*       out    = (float*)d_out;

    init_kernel<<<1, 1>>>();
    normalize_kernel<<<NN / 8, 256>>>(z);                 // 8 warps/block
    gemm_kernel<<<dim3(NN / BN, NN / BM), 256>>>();
    stats_kernel<<<NN, 256>>>();
    neg_kernel<<<NN, 256>>>(labels);
    pos_kernel<<<(NN / 2 + 255) / 256, 256>>>(labels);
    finalize_kernel<<<1, 1>>>(out);
}

// round 2
// speedup vs baseline: 2.8992x; 2.8992x over previous
#include <cuda_runtime.h>
#include <math.h>
#include <stdint.h>

#define NN 8192
#define DD 512
#define TEMP_INV 5.0f

// Scratch (device globals: no allocation allowed)
__device__ float  g_zn[(size_t)NN * DD];         // 16 MB normalized rows (tf32-rounded)
__device__ float  g_sim[(size_t)NN * NN];        // 256 MB Gram matrix
__device__ float  g_u[NN];                       // mean of sim per column j (= 1 - mu_j)
__device__ float  g_A[NN];                       // 1/(2*var_j)
__device__ double g_neg;
__device__ double g_pos;

// ---------------------------------------------------------------------------
__global__ void init_kernel() { g_neg = 0.0; g_pos = 0.0; }

__device__ __forceinline__ float tf32_rna(float x) {
    uint32_t u;
    asm("cvt.rna.tf32.f32 %0, %1;" : "=r"(u) : "f"(x));
    return __uint_as_float(u);
}

// ---------------------------------------------------------------------------
// Row normalize + round to tf32 (so the GEMM inputs are exact tf32 values).
__global__ void normalize_kernel(const float* __restrict__ z) {
    int warp = (blockIdx.x * blockDim.x + threadIdx.x) >> 5;
    int lane = threadIdx.x & 31;
    if (warp >= NN) return;
    const float4* zr = (const float4*)(z + (size_t)warp * DD);
    float4 v[4];
    float ss = 0.f;
#pragma unroll
    for (int t = 0; t < 4; t++) {
        v[t] = zr[lane + 32 * t];
        ss += v[t].x * v[t].x + v[t].y * v[t].y + v[t].z * v[t].z + v[t].w * v[t].w;
    }
#pragma unroll
    for (int o = 16; o > 0; o >>= 1) ss += __shfl_xor_sync(0xffffffffu, ss, o);
    float inv = 1.0f / fmaxf(sqrtf(ss), 1e-12f);
    float4* outp = (float4*)(g_zn + (size_t)warp * DD);
#pragma unroll
    for (int t = 0; t < 4; t++) {
        float4 o4 = make_float4(tf32_rna(v[t].x * inv), tf32_rna(v[t].y * inv),
                                tf32_rna(v[t].z * inv), tf32_rna(v[t].w * inv));
        outp[lane + 32 * t] = o4;
    }
}

// ---------------------------------------------------------------------------
// TF32 tensor-core GEMM: sim = zn * zn^T (symmetric, upper-tri blocks + mirror)
// Block 128x128, BK=32, 256 threads = 8 warps (2x4), warp tile 64x32,
// mma.sync m16n8k8 tf32. Smem layout [row][k] pitch 36 floats:
//  - frag LDS bank = 4*g + c  -> conflict-free
//  - STS.128 staging conflict-free, straight copy from gmem (no transpose)
#define SPITCH 36

__device__ __forceinline__ void mma_tf32(float c[4], uint32_t a0, uint32_t a1,
                                         uint32_t a2, uint32_t a3,
                                         uint32_t b0, uint32_t b1) {
    asm volatile(
        "mma.sync.aligned.m16n8k8.row.col.f32.tf32.tf32.f32 "
        "{%0,%1,%2,%3}, {%4,%5,%6,%7}, {%8,%9}, {%0,%1,%2,%3};"
        : "+f"(c[0]), "+f"(c[1]), "+f"(c[2]), "+f"(c[3])
        : "r"(a0), "r"(a1), "r"(a2), "r"(a3), "r"(b0), "r"(b1));
}

__global__ void __launch_bounds__(256, 2) gemm_kernel() {
    int bc = blockIdx.x, br = blockIdx.y;
    if (br > bc) return;  // symmetry

    __shared__ float sA[128 * SPITCH];
    __shared__ float sB[128 * SPITCH];

    int tid = threadIdx.x;
    int wid = tid >> 5, lane = tid & 31;
    int wm = wid >> 2, wn = wid & 3;   // warp tile origin: rows wm*64, cols wn*32
    int g = lane >> 2, c = lane & 3;

    // staging: 2 threads per row, each loads 4 float4 (16 floats of the k-window)
    int sm = tid >> 1;
    int half = tid & 1;
    const float4* Z4 = (const float4*)g_zn;
    const float4* Arow = Z4 + (size_t)(br * 128 + sm) * (DD / 4);
    const float4* Brow = Z4 + (size_t)(bc * 128 + sm) * (DD / 4);
    float4* stA = (float4*)(sA + sm * SPITCH + half * 16);
    float4* stB = (float4*)(sB + sm * SPITCH + half * 16);

    float acc[4][4][4];
#pragma unroll
    for (int i = 0; i < 4; i++)
#pragma unroll
        for (int j = 0; j < 4; j++)
#pragma unroll
            for (int r = 0; r < 4; r++) acc[i][j][r] = 0.f;

    float4 pa[4], pb[4];
    // prefetch stage 0
#pragma unroll
    for (int it = 0; it < 4; it++) {
        pa[it] = Arow[half * 4 + it];
        pb[it] = Brow[half * 4 + it];
    }

    const float* fA = sA + (wm * 64 + g) * SPITCH;     // + mi*16*SPITCH (+8*SPITCH)
    const float* fB = sB + (wn * 32 + g) * SPITCH;     // + nj*8*SPITCH

    for (int kk = 0; kk < DD; kk += 32) {
#pragma unroll
        for (int it = 0; it < 4; it++) { stA[it] = pa[it]; stB[it] = pb[it]; }
        __syncthreads();

        if (kk + 32 < DD) {
            int base = (kk + 32) / 4 + half * 4;
#pragma unroll
            for (int it = 0; it < 4; it++) {
                pa[it] = Arow[base + it];
                pb[it] = Brow[base + it];
            }
        }

#pragma unroll
        for (int ks = 0; ks < 4; ks++) {
            int k0 = ks * 8 + c;
            uint32_t bf[4][2];
#pragma unroll
            for (int nj = 0; nj < 4; nj++) {
                bf[nj][0] = __float_as_uint(fB[nj * 8 * SPITCH + k0]);
                bf[nj][1] = __float_as_uint(fB[nj * 8 * SPITCH + k0 + 4]);
            }
#pragma unroll
            for (int mi = 0; mi < 4; mi++) {
                uint32_t a0 = __float_as_uint(fA[mi * 16 * SPITCH + k0]);
                uint32_t a1 = __float_as_uint(fA[(mi * 16 + 8) * SPITCH + k0]);
                uint32_t a2 = __float_as_uint(fA[mi * 16 * SPITCH + k0 + 4]);
                uint32_t a3 = __float_as_uint(fA[(mi * 16 + 8) * SPITCH + k0 + 4]);
#pragma unroll
                for (int nj = 0; nj < 4; nj++)
                    mma_tf32(acc[mi][nj], a0, a1, a2, a3, bf[nj][0], bf[nj][1]);
            }
        }
        __syncthreads();
    }

    // epilogue: direct tile + mirror
    int Rb = br * 128 + wm * 64 + g;
    int Cb = bc * 128 + wn * 32 + 2 * c;
#pragma unroll
    for (int mi = 0; mi < 4; mi++) {
#pragma unroll
        for (int nj = 0; nj < 4; nj++) {
            int R0 = Rb + mi * 16, R1 = R0 + 8;
            int C = Cb + nj * 8;
            float2* p0 = (float2*)(g_sim + (size_t)R0 * NN + C);
            float2* p1 = (float2*)(g_sim + (size_t)R1 * NN + C);
            *p0 = make_float2(acc[mi][nj][0], acc[mi][nj][1]);
            *p1 = make_float2(acc[mi][nj][2], acc[mi][nj][3]);
        }
    }
    if (br != bc) {
#pragma unroll
        for (int mi = 0; mi < 4; mi++) {
#pragma unroll
            for (int nj = 0; nj < 4; nj++) {
                int R0 = Rb + mi * 16, R1 = R0 + 8;
                int C = Cb + nj * 8;
                g_sim[(size_t)C * NN + R0]       = acc[mi][nj][0];
                g_sim[(size_t)(C + 1) * NN + R0] = acc[mi][nj][1];
                g_sim[(size_t)C * NN + R1]       = acc[mi][nj][2];
                g_sim[(size_t)(C + 1) * NN + R1] = acc[mi][nj][3];
            }
        }
    }
}

// ---------------------------------------------------------------------------
// Per-row mean/var of sim: fp32 float4-wise partials (independent chains),
// widen to double only for the 256-wide tree + final cancellation-sensitive math.
__global__ void stats_kernel() {
    int i = blockIdx.x;
    const float4* row = (const float4*)(g_sim + (size_t)i * NN);
    float4 s4 = make_float4(0, 0, 0, 0), q4 = make_float4(0, 0, 0, 0);
    for (int j = threadIdx.x; j < NN / 4; j += 256) {
        float4 v = row[j];
        s4.x += v.x; s4.y += v.y; s4.z += v.z; s4.w += v.w;
        q4.x = fmaf(v.x, v.x, q4.x); q4.y = fmaf(v.y, v.y, q4.y);
        q4.z = fmaf(v.z, v.z, q4.z); q4.w = fmaf(v.w, v.w, q4.w);
    }
    double s  = (double)s4.x + s4.y + s4.z + s4.w;
    double s2 = (double)q4.x + q4.y + q4.z + q4.w;
    __shared__ double sh[256];
    __shared__ double sh2[256];
    int t = threadIdx.x;
    sh[t] = s; sh2[t] = s2;
    __syncthreads();
    for (int st = 128; st > 0; st >>= 1) {
        if (t < st) { sh[t] += sh[t + st]; sh2[t] += sh2[t + st]; }
        __syncthreads();
    }
    if (t == 0) {
        double smean = sh[0] / (double)NN;
        // var(dist) == var(sim); E[dist]=1-smean
        double var = (sh2[0] - (double)NN * smean * smean) / (double)(NN - 1);
        g_u[i] = (float)smean;                  // 1 - mu_j
        g_A[i] = (float)(1.0 / (2.0 * var));
    }
}

// ---------------------------------------------------------------------------
// Negative sum: exp(5*s + A_j*(u_j - s)^2) over labels[i]!=labels[j].
// fp32 per-thread partial (32 terms), double only in the reduction.
__global__ void neg_kernel(const int* __restrict__ labels) {
    int i = blockIdx.x;
    int li = __ldg(&labels[i]);
    const float4* row = (const float4*)(g_sim + (size_t)i * NN);
    const int4* lab4 = (const int4*)labels;
    float accf = 0.f;
    for (int j4 = threadIdx.x; j4 < NN / 4; j4 += 256) {
        float4 v = row[j4];
        int4 L = __ldg(&lab4[j4]);
        int j = 4 * j4;
        if (L.x != li) { float t = __ldg(&g_u[j])     - v.x; accf += __expf(fmaf(t * t, __ldg(&g_A[j]),     v.x * TEMP_INV)); }
        if (L.y != li) { float t = __ldg(&g_u[j + 1]) - v.y; accf += __expf(fmaf(t * t, __ldg(&g_A[j + 1]), v.y * TEMP_INV)); }
        if (L.z != li) { float t = __ldg(&g_u[j + 2]) - v.z; accf += __expf(fmaf(t * t, __ldg(&g_A[j + 2]), v.z * TEMP_INV)); }
        if (L.w != li) { float t = __ldg(&g_u[j + 3]) - v.w; accf += __expf(fmaf(t * t, __ldg(&g_A[j + 3]), v.w * TEMP_INV)); }
    }
    __shared__ double sh[256];
    int t = threadIdx.x;
    sh[t] = (double)accf;
    __syncthreads();
    for (int st = 128; st > 0; st >>= 1) {
        if (t < st) sh[t] += sh[t + st];
        __syncthreads();
    }
    if (t == 0) atomicAdd(&g_neg, sh[0]);
}

// ---------------------------------------------------------------------------
__global__ void pos_kernel(const int* __restrict__ labels) {
    int i = blockIdx.x * blockDim.x + threadIdx.x;
    double v = 0.0;
    const int b = NN / 2;
    if (i < b && labels[i] == labels[i + b]) {
        float s = g_sim[(size_t)i * NN + (i + b)];
        v = (double)expf(s * TEMP_INV);
    }
    __shared__ double sh[256];
    int t = threadIdx.x;
    sh[t] = v;
    __syncthreads();
    for (int st = 128; st > 0; st >>= 1) {
        if (t < st) sh[t] += sh[t + st];
        __syncthreads();
    }
    if (t == 0) atomicAdd(&g_pos, sh[0]);
}

// ---------------------------------------------------------------------------
__global__ void finalize_kernel(float* out) {
    out[0] = (float)(-log(g_pos / (g_pos + g_neg)));
}

// ---------------------------------------------------------------------------
extern "C" void kernel_launch(void* const* d_in, const int* in_sizes, int n_in,
                              void* d_out, int out_size) {
    const float* z      = (const float*)d_in[0];
    const int*   labels = (const int*)d_in[1];
    float*       out    = (float*)d_out;

    init_kernel<<<1, 1>>>();
    normalize_kernel<<<NN / 8, 256>>>(z);
    gemm_kernel<<<dim3(NN / 128, NN / 128), 256>>>();
    stats_kernel<<<NN, 256>>>();
    neg_kernel<<<NN, 256>>>(labels);
    pos_kernel<<<(NN / 2 + 255) / 256, 256>>>(labels);
    finalize_kernel<<<1, 1>>>(out);
}

// round 4
// speedup vs baseline: 3.4998x; 1.2071x over previous
#include <cuda_runtime.h>
#include <math.h>
#include <stdint.h>

#define NN 8192
#define DD 512
#define TEMP_INV 5.0f

// Scratch (device globals: no allocation allowed)
__device__ float  g_zn[(size_t)NN * DD];          // 16 MB normalized rows (tf32-rounded)
__device__ float  g_sim[(size_t)NN * NN];         // 256 MB Gram matrix
__device__ float2 g_colstat[NN];                  // per-column {sum, sumsq} of sim
__device__ float2 g_uA[NN];                       // {mean_sim_j, 1/(2*var_j)}
__device__ double g_neg;
__device__ double g_pos;

// ---------------------------------------------------------------------------
__global__ void init_kernel() {
    int j = blockIdx.x * blockDim.x + threadIdx.x;
    if (j < NN) g_colstat[j] = make_float2(0.f, 0.f);
    if (j == 0) { g_neg = 0.0; g_pos = 0.0; }
}

__device__ __forceinline__ float tf32_rna(float x) {
    uint32_t u;
    asm("cvt.rna.tf32.f32 %0, %1;" : "=r"(u) : "f"(x));
    return __uint_as_float(u);
}

// ---------------------------------------------------------------------------
// Row normalize + round to tf32 (so the GEMM inputs are exact tf32 values).
__global__ void normalize_kernel(const float* __restrict__ z) {
    int warp = (blockIdx.x * blockDim.x + threadIdx.x) >> 5;
    int lane = threadIdx.x & 31;
    if (warp >= NN) return;
    const float4* zr = (const float4*)(z + (size_t)warp * DD);
    float4 v[4];
    float ss = 0.f;
#pragma unroll
    for (int t = 0; t < 4; t++) {
        v[t] = zr[lane + 32 * t];
        ss += v[t].x * v[t].x + v[t].y * v[t].y + v[t].z * v[t].z + v[t].w * v[t].w;
    }
#pragma unroll
    for (int o = 16; o > 0; o >>= 1) ss += __shfl_xor_sync(0xffffffffu, ss, o);
    float inv = 1.0f / fmaxf(sqrtf(ss), 1e-12f);
    float4* outp = (float4*)(g_zn + (size_t)warp * DD);
#pragma unroll
    for (int t = 0; t < 4; t++) {
        float4 o4 = make_float4(tf32_rna(v[t].x * inv), tf32_rna(v[t].y * inv),
                                tf32_rna(v[t].z * inv), tf32_rna(v[t].w * inv));
        outp[lane + 32 * t] = o4;
    }
}

// ---------------------------------------------------------------------------
// TF32 tensor-core GEMM with fused column/row stats in the epilogue.
// Block 128x128, BK=32, 256 threads (8 warps 2x4), warp tile 64x32.
#define SPITCH 36

__device__ __forceinline__ void mma_tf32(float c[4], uint32_t a0, uint32_t a1,
                                         uint32_t a2, uint32_t a3,
                                         uint32_t b0, uint32_t b1) {
    asm volatile(
        "mma.sync.aligned.m16n8k8.row.col.f32.tf32.tf32.f32 "
        "{%0,%1,%2,%3}, {%4,%5,%6,%7}, {%8,%9}, {%0,%1,%2,%3};"
        : "+f"(c[0]), "+f"(c[1]), "+f"(c[2]), "+f"(c[3])
        : "r"(a0), "r"(a1), "r"(a2), "r"(a3), "r"(b0), "r"(b1));
}

__global__ void __launch_bounds__(256, 2) gemm_kernel() {
    int bc = blockIdx.x, br = blockIdx.y;
    if (br > bc) return;  // symmetry

    __shared__ float sA[128 * SPITCH];
    __shared__ float sB[128 * SPITCH];
    __shared__ float red[4][128];   // [0]=colsum [1]=colsq [2]=rowsum [3]=rowsq

    int tid = threadIdx.x;
    int wid = tid >> 5, lane = tid & 31;
    int wm = wid >> 2, wn = wid & 3;
    int g = lane >> 2, c = lane & 3;

    int sm = tid >> 1;
    int half = tid & 1;
    const float4* Z4 = (const float4*)g_zn;
    const float4* Arow = Z4 + (size_t)(br * 128 + sm) * (DD / 4);
    const float4* Brow = Z4 + (size_t)(bc * 128 + sm) * (DD / 4);
    float4* stA = (float4*)(sA + sm * SPITCH + half * 16);
    float4* stB = (float4*)(sB + sm * SPITCH + half * 16);

    float acc[4][4][4];
#pragma unroll
    for (int i = 0; i < 4; i++)
#pragma unroll
        for (int j = 0; j < 4; j++)
#pragma unroll
            for (int r = 0; r < 4; r++) acc[i][j][r] = 0.f;

    float4 pa[4], pb[4];
#pragma unroll
    for (int it = 0; it < 4; it++) {
        pa[it] = Arow[half * 4 + it];
        pb[it] = Brow[half * 4 + it];
    }

    const float* fA = sA + (wm * 64 + g) * SPITCH;
    const float* fB = sB + (wn * 32 + g) * SPITCH;

    for (int kk = 0; kk < DD; kk += 32) {
#pragma unroll
        for (int it = 0; it < 4; it++) { stA[it] = pa[it]; stB[it] = pb[it]; }
        __syncthreads();

        if (kk + 32 < DD) {
            int base = (kk + 32) / 4 + half * 4;
#pragma unroll
            for (int it = 0; it < 4; it++) {
                pa[it] = Arow[base + it];
                pb[it] = Brow[base + it];
            }
        }

#pragma unroll
        for (int ks = 0; ks < 4; ks++) {
            int k0 = ks * 8 + c;
            uint32_t bf[4][2];
#pragma unroll
            for (int nj = 0; nj < 4; nj++) {
                bf[nj][0] = __float_as_uint(fB[nj * 8 * SPITCH + k0]);
                bf[nj][1] = __float_as_uint(fB[nj * 8 * SPITCH + k0 + 4]);
            }
#pragma unroll
            for (int mi = 0; mi < 4; mi++) {
                uint32_t a0 = __float_as_uint(fA[mi * 16 * SPITCH + k0]);
                uint32_t a1 = __float_as_uint(fA[(mi * 16 + 8) * SPITCH + k0]);
                uint32_t a2 = __float_as_uint(fA[mi * 16 * SPITCH + k0 + 4]);
                uint32_t a3 = __float_as_uint(fA[(mi * 16 + 8) * SPITCH + k0 + 4]);
#pragma unroll
                for (int nj = 0; nj < 4; nj++)
                    mma_tf32(acc[mi][nj], a0, a1, a2, a3, bf[nj][0], bf[nj][1]);
            }
        }
        __syncthreads();
    }

    // ---- write sim: direct tile + mirror ----
    int Rb = br * 128 + wm * 64 + g;
    int Cb = bc * 128 + wn * 32 + 2 * c;
#pragma unroll
    for (int mi = 0; mi < 4; mi++) {
#pragma unroll
        for (int nj = 0; nj < 4; nj++) {
            int R0 = Rb + mi * 16, R1 = R0 + 8;
            int C = Cb + nj * 8;
            float2* p0 = (float2*)(g_sim + (size_t)R0 * NN + C);
            float2* p1 = (float2*)(g_sim + (size_t)R1 * NN + C);
            *p0 = make_float2(acc[mi][nj][0], acc[mi][nj][1]);
            *p1 = make_float2(acc[mi][nj][2], acc[mi][nj][3]);
        }
    }
    if (br != bc) {
#pragma unroll
        for (int mi = 0; mi < 4; mi++) {
#pragma unroll
            for (int nj = 0; nj < 4; nj++) {
                int R0 = Rb + mi * 16, R1 = R0 + 8;
                int C = Cb + nj * 8;
                g_sim[(size_t)C * NN + R0]       = acc[mi][nj][0];
                g_sim[(size_t)(C + 1) * NN + R0] = acc[mi][nj][1];
                g_sim[(size_t)C * NN + R1]       = acc[mi][nj][2];
                g_sim[(size_t)(C + 1) * NN + R1] = acc[mi][nj][3];
            }
        }
    }

    // ---- fused stats: column sums (direct) + row sums (mirror columns) ----
    for (int t = tid; t < 512; t += 256) ((float*)red)[t] = 0.f;
    __syncthreads();

#pragma unroll
    for (int nj = 0; nj < 4; nj++) {
#pragma unroll
        for (int r2 = 0; r2 < 2; r2++) {
            float s = 0.f, q = 0.f;
#pragma unroll
            for (int mi = 0; mi < 4; mi++) {
                float x = acc[mi][nj][r2];     s += x; q = fmaf(x, x, q);
                float y = acc[mi][nj][r2 + 2]; s += y; q = fmaf(y, y, q);
            }
            int col = wn * 32 + nj * 8 + 2 * c + r2;
            atomicAdd(&red[0][col], s);
            atomicAdd(&red[1][col], q);
        }
    }
    if (br != bc) {
#pragma unroll
        for (int mi = 0; mi < 4; mi++) {
#pragma unroll
            for (int h = 0; h < 2; h++) {
                float s = 0.f, q = 0.f;
#pragma unroll
                for (int nj = 0; nj < 4; nj++) {
                    float x = acc[mi][nj][2 * h];     s += x; q = fmaf(x, x, q);
                    float y = acc[mi][nj][2 * h + 1]; s += y; q = fmaf(y, y, q);
                }
                int row = wm * 64 + mi * 16 + 8 * h + g;
                atomicAdd(&red[2][row], s);
                atomicAdd(&red[3][row], q);
            }
        }
    }
    __syncthreads();

    if (tid < 128) {
        atomicAdd(&g_colstat[bc * 128 + tid].x, red[0][tid]);
        atomicAdd(&g_colstat[bc * 128 + tid].y, red[1][tid]);
    } else if (br != bc) {
        int r = tid - 128;
        atomicAdd(&g_colstat[br * 128 + r].x, red[2][r]);
        atomicAdd(&g_colstat[br * 128 + r].y, red[3][r]);
    }
}

// ---------------------------------------------------------------------------
// Convert column sums -> {mean_sim, 1/(2*var)} (ddof=1, torch.std unbiased)
__global__ void stats_fin_kernel() {
    int j = blockIdx.x * blockDim.x + threadIdx.x;
    if (j >= NN) return;
    float2 cs = g_colstat[j];
    double smean = (double)cs.x / (double)NN;
    double var = ((double)cs.y - (double)NN * smean * smean) / (double)(NN - 1);
    g_uA[j] = make_float2((float)smean, (float)(1.0 / (2.0 * var)));
}

// ---------------------------------------------------------------------------
// Negative sum: 4 rows per block, shared labels/uA loads, selp masking.
__device__ __forceinline__ float neg_term(int lj, int li, float s, float u, float A) {
    float t = u - s;
    float e = fmaf(t * t, A, s * TEMP_INV);
    return (lj != li) ? __expf(e) : 0.f;
}

__global__ void __launch_bounds__(256) neg_kernel(const int* __restrict__ labels) {
    int i0 = blockIdx.x * 4;
    int li0 = __ldg(&labels[i0]);
    int li1 = __ldg(&labels[i0 + 1]);
    int li2 = __ldg(&labels[i0 + 2]);
    int li3 = __ldg(&labels[i0 + 3]);
    const float4* r0 = (const float4*)(g_sim + (size_t)i0 * NN);
    const float4* r1 = r0 + NN / 4;
    const float4* r2 = r1 + NN / 4;
    const float4* r3 = r2 + NN / 4;
    const int4* lab4 = (const int4*)labels;
    const float4* uA4 = (const float4*)g_uA;

    float acc = 0.f;
    for (int j4 = threadIdx.x; j4 < NN / 4; j4 += 256) {
        int4 L = __ldg(&lab4[j4]);
        float4 ua = __ldg(&uA4[2 * j4]);       // (u0, A0, u1, A1)
        float4 ub = __ldg(&uA4[2 * j4 + 1]);   // (u2, A2, u3, A3)
        float4 v0 = r0[j4];
        float4 v1 = r1[j4];
        float4 v2 = r2[j4];
        float4 v3 = r3[j4];

        acc += neg_term(L.x, li0, v0.x, ua.x, ua.y);
        acc += neg_term(L.y, li0, v0.y, ua.z, ua.w);
        acc += neg_term(L.z, li0, v0.z, ub.x, ub.y);
        acc += neg_term(L.w, li0, v0.w, ub.z, ub.w);

        acc += neg_term(L.x, li1, v1.x, ua.x, ua.y);
        acc += neg_term(L.y, li1, v1.y, ua.z, ua.w);
        acc += neg_term(L.z, li1, v1.z, ub.x, ub.y);
        acc += neg_term(L.w, li1, v1.w, ub.z, ub.w);

        acc += neg_term(L.x, li2, v2.x, ua.x, ua.y);
        acc += neg_term(L.y, li2, v2.y, ua.z, ua.w);
        acc += neg_term(L.z, li2, v2.z, ub.x, ub.y);
        acc += neg_term(L.w, li2, v2.w, ub.z, ub.w);

        acc += neg_term(L.x, li3, v3.x, ua.x, ua.y);
        acc += neg_term(L.y, li3, v3.y, ua.z, ua.w);
        acc += neg_term(L.z, li3, v3.z, ub.x, ub.y);
        acc += neg_term(L.w, li3, v3.w, ub.z, ub.w);
    }

    __shared__ double sh[256];
    int t = threadIdx.x;
    sh[t] = (double)acc;
    __syncthreads();
    for (int st = 128; st > 0; st >>= 1) {
        if (t < st) sh[t] += sh[t + st];
        __syncthreads();
    }
    if (t == 0) atomicAdd(&g_neg, sh[0]);
}

// ---------------------------------------------------------------------------
__global__ void pos_kernel(const int* __restrict__ labels) {
    int i = blockIdx.x * blockDim.x + threadIdx.x;
    double v = 0.0;
    const int b = NN / 2;
    if (i < b && labels[i] == labels[i + b]) {
        float s = g_sim[(size_t)i * NN + (i + b)];
        v = (double)expf(s * TEMP_INV);
    }
    __shared__ double sh[256];
    int t = threadIdx.x;
    sh[t] = v;
    __syncthreads();
    for (int st = 128; st > 0; st >>= 1) {
        if (t < st) sh[t] += sh[t + st];
        __syncthreads();
    }
    if (t == 0) atomicAdd(&g_pos, sh[0]);
}

// ---------------------------------------------------------------------------
__global__ void finalize_kernel(float* out) {
    out[0] = (float)(-log(g_pos / (g_pos + g_neg)));
}

// ---------------------------------------------------------------------------
extern "C" void kernel_launch(void* const* d_in, const int* in_sizes, int n_in,
                              void* d_out, int out_size) {
    const float* z      = (const float*)d_in[0];
    const int*   labels = (const int*)d_in[1];
    float*       out    = (float*)d_out;

    init_kernel<<<NN / 256, 256>>>();
    normalize_kernel<<<NN / 8, 256>>>(z);
    gemm_kernel<<<dim3(NN / 128, NN / 128), 256>>>();
    stats_fin_kernel<<<NN / 256, 256>>>();
    neg_kernel<<<NN / 4, 256>>>(labels);
    pos_kernel<<<(NN / 2 + 255) / 256, 256>>>(labels);
    finalize_kernel<<<1, 1>>>(out);
}

// round 6
// speedup vs baseline: 4.0880x; 1.1681x over previous
#include <cuda_runtime.h>
#include <math.h>
#include <stdint.h>

#define NN 8192
#define DD 512
#define TEMP_INV 5.0f

// Scratch (device globals: no allocation allowed)
__device__ float  g_zn[(size_t)NN * DD];          // 16 MB normalized rows (tf32-rounded)
__device__ float  g_sim[(size_t)NN * NN];         // 256 MB Gram matrix
__device__ float2 g_colstat[NN];                  // per-column {sum, sumsq} of sim
__device__ float2 g_uA[NN];                       // {mean_sim_j, 1/(2*var_j)}
__device__ double g_neg;
__device__ double g_pos;

// ---------------------------------------------------------------------------
__global__ void init_kernel() {
    int j = blockIdx.x * blockDim.x + threadIdx.x;
    if (j < NN) g_colstat[j] = make_float2(0.f, 0.f);
    if (j == 0) { g_neg = 0.0; g_pos = 0.0; }
}

__global__ void nop_kernel() {}   // pads launch index so ncu (idx 3) captures the GEMM

__device__ __forceinline__ float tf32_rna(float x) {
    uint32_t u;
    asm("cvt.rna.tf32.f32 %0, %1;" : "=r"(u) : "f"(x));
    return __uint_as_float(u);
}

// ---------------------------------------------------------------------------
__global__ void normalize_kernel(const float* __restrict__ z) {
    int warp = (blockIdx.x * blockDim.x + threadIdx.x) >> 5;
    int lane = threadIdx.x & 31;
    if (warp >= NN) return;
    const float4* zr = (const float4*)(z + (size_t)warp * DD);
    float4 v[4];
    float ss = 0.f;
#pragma unroll
    for (int t = 0; t < 4; t++) {
        v[t] = zr[lane + 32 * t];
        ss += v[t].x * v[t].x + v[t].y * v[t].y + v[t].z * v[t].z + v[t].w * v[t].w;
    }
#pragma unroll
    for (int o = 16; o > 0; o >>= 1) ss += __shfl_xor_sync(0xffffffffu, ss, o);
    float inv = 1.0f / fmaxf(sqrtf(ss), 1e-12f);
    float4* outp = (float4*)(g_zn + (size_t)warp * DD);
#pragma unroll
    for (int t = 0; t < 4; t++) {
        float4 o4 = make_float4(tf32_rna(v[t].x * inv), tf32_rna(v[t].y * inv),
                                tf32_rna(v[t].z * inv), tf32_rna(v[t].w * inv));
        outp[lane + 32 * t] = o4;
    }
}

// ---------------------------------------------------------------------------
// TF32 mma.sync GEMM, cp.async double-buffered staging, fused stats epilogue.
// Block 128x128, BK=32, 256 threads (8 warps 2x4), warp tile 64x32.
// Smem [row][k] pitch 36 floats; frag LDS bank = 4*g + c (conflict-free).
#define SPITCH 36
#define STAGE_BYTES 36864     // (128*36*4) * 2 tiles (A then B: A 18432, B 18432)

__device__ __forceinline__ void mma_tf32(float c[4], uint32_t a0, uint32_t a1,
                                         uint32_t a2, uint32_t a3,
                                         uint32_t b0, uint32_t b1) {
    asm volatile(
        "mma.sync.aligned.m16n8k8.row.col.f32.tf32.tf32.f32 "
        "{%0,%1,%2,%3}, {%4,%5,%6,%7}, {%8,%9}, {%0,%1,%2,%3};"
        : "+f"(c[0]), "+f"(c[1]), "+f"(c[2]), "+f"(c[3])
        : "r"(a0), "r"(a1), "r"(a2), "r"(a3), "r"(b0), "r"(b1));
}

__device__ __forceinline__ uint32_t smem_u32(const void* p) {
    uint32_t a;
    asm("{ .reg .u64 t; cvta.to.shared.u64 t, %1; cvt.u32.u64 %0, t; }" : "=r"(a) : "l"(p));
    return a;
}

__device__ __forceinline__ void stage_chunk_async(uint32_t sb, int buf, int br, int bc, int chunk) {
    uint32_t bA = sb + buf * STAGE_BYTES;
    uint32_t bB = bA + 18432;
    int t = threadIdx.x;
#pragma unroll
    for (int i = 0; i < 4; i++) {
        int idx = t + 256 * i;            // 0..1023
        int row = idx >> 3, q = idx & 7;  // row 0..127, q 0..7 (16B quad of 32-float k-window)
        uint32_t off = (uint32_t)(row * 144 + q * 16);   // 144 = SPITCH*4, 16B aligned
        const float* ga = &g_zn[(size_t)(br * 128 + row) * DD + chunk * 32 + q * 4];
        const float* gb = &g_zn[(size_t)(bc * 128 + row) * DD + chunk * 32 + q * 4];
        asm volatile("cp.async.ca.shared.global [%0], [%1], 16;" :: "r"(bA + off), "l"(ga));
        asm volatile("cp.async.ca.shared.global [%0], [%1], 16;" :: "r"(bB + off), "l"(gb));
    }
}

#define GEMM_SMEM (2 * STAGE_BYTES + 2048)   // 2 stages + red[4][128]

__global__ void __launch_bounds__(256, 2) gemm_kernel() {
    // triangular block index -> (br, bc), br <= bc
    int lin = blockIdx.x;
    int br = (int)(64.5 - sqrt(64.5 * 64.5 - 2.0 * (double)lin));
    while (br * 64 - br * (br - 1) / 2 > lin) br--;
    while ((br + 1) * 64 - (br + 1) * br / 2 <= lin) br++;
    int bc = br + lin - (br * 64 - br * (br - 1) / 2);

    extern __shared__ char smem[];
    uint32_t sb = smem_u32(smem);
    float* red = (float*)(smem + 2 * STAGE_BYTES);   // [4][128]

    int tid = threadIdx.x;
    int wid = tid >> 5, lane = tid & 31;
    int wm = wid >> 2, wn = wid & 3;
    int g = lane >> 2, c = lane & 3;

    float acc[4][4][4];
#pragma unroll
    for (int i = 0; i < 4; i++)
#pragma unroll
        for (int j = 0; j < 4; j++)
#pragma unroll
            for (int r = 0; r < 4; r++) acc[i][j][r] = 0.f;

    stage_chunk_async(sb, 0, br, bc, 0);
    asm volatile("cp.async.commit_group;");

    for (int ck = 0; ck < 16; ck++) {
        int buf = ck & 1;
        if (ck + 1 < 16) stage_chunk_async(sb, 1 - buf, br, bc, ck + 1);
        asm volatile("cp.async.commit_group;");
        asm volatile("cp.async.wait_group 1;");
        __syncthreads();

        const float* fA = (const float*)(smem + buf * STAGE_BYTES) + (wm * 64 + g) * SPITCH;
        const float* fB = (const float*)(smem + buf * STAGE_BYTES + 18432) + (wn * 32 + g) * SPITCH;
#pragma unroll
        for (int ks = 0; ks < 4; ks++) {
            int k0 = ks * 8 + c;
            uint32_t bf[4][2];
#pragma unroll
            for (int nj = 0; nj < 4; nj++) {
                bf[nj][0] = __float_as_uint(fB[nj * 8 * SPITCH + k0]);
                bf[nj][1] = __float_as_uint(fB[nj * 8 * SPITCH + k0 + 4]);
            }
#pragma unroll
            for (int mi = 0; mi < 4; mi++) {
                uint32_t a0 = __float_as_uint(fA[mi * 16 * SPITCH + k0]);
                uint32_t a1 = __float_as_uint(fA[(mi * 16 + 8) * SPITCH + k0]);
                uint32_t a2 = __float_as_uint(fA[mi * 16 * SPITCH + k0 + 4]);
                uint32_t a3 = __float_as_uint(fA[(mi * 16 + 8) * SPITCH + k0 + 4]);
#pragma unroll
                for (int nj = 0; nj < 4; nj++)
                    mma_tf32(acc[mi][nj], a0, a1, a2, a3, bf[nj][0], bf[nj][1]);
            }
        }
        __syncthreads();
    }

    // ---- write sim: direct tile + mirror ----
    int Rb = br * 128 + wm * 64 + g;
    int Cb = bc * 128 + wn * 32 + 2 * c;
#pragma unroll
    for (int mi = 0; mi < 4; mi++) {
#pragma unroll
        for (int nj = 0; nj < 4; nj++) {
            int R0 = Rb + mi * 16, R1 = R0 + 8;
            int C = Cb + nj * 8;
            float2* p0 = (float2*)(g_sim + (size_t)R0 * NN + C);
            float2* p1 = (float2*)(g_sim + (size_t)R1 * NN + C);
            *p0 = make_float2(acc[mi][nj][0], acc[mi][nj][1]);
            *p1 = make_float2(acc[mi][nj][2], acc[mi][nj][3]);
        }
    }
    if (br != bc) {
#pragma unroll
        for (int mi = 0; mi < 4; mi++) {
#pragma unroll
            for (int nj = 0; nj < 4; nj++) {
                int R0 = Rb + mi * 16, R1 = R0 + 8;
                int C = Cb + nj * 8;
                g_sim[(size_t)C * NN + R0]       = acc[mi][nj][0];
                g_sim[(size_t)(C + 1) * NN + R0] = acc[mi][nj][1];
                g_sim[(size_t)C * NN + R1]       = acc[mi][nj][2];
                g_sim[(size_t)(C + 1) * NN + R1] = acc[mi][nj][3];
            }
        }
    }

    // ---- fused stats: column sums (direct) + row sums (mirror columns) ----
    for (int t = tid; t < 512; t += 256) red[t] = 0.f;
    __syncthreads();

#pragma unroll
    for (int nj = 0; nj < 4; nj++) {
#pragma unroll
        for (int r2 = 0; r2 < 2; r2++) {
            float s = 0.f, q = 0.f;
#pragma unroll
            for (int mi = 0; mi < 4; mi++) {
                float x = acc[mi][nj][r2];     s += x; q = fmaf(x, x, q);
                float y = acc[mi][nj][r2 + 2]; s += y; q = fmaf(y, y, q);
            }
            int col = wn * 32 + nj * 8 + 2 * c + r2;
            atomicAdd(&red[col], s);
            atomicAdd(&red[128 + col], q);
        }
    }
    if (br != bc) {
#pragma unroll
        for (int mi = 0; mi < 4; mi++) {
#pragma unroll
            for (int h = 0; h < 2; h++) {
                float s = 0.f, q = 0.f;
#pragma unroll
                for (int nj = 0; nj < 4; nj++) {
                    float x = acc[mi][nj][2 * h];     s += x; q = fmaf(x, x, q);
                    float y = acc[mi][nj][2 * h + 1]; s += y; q = fmaf(y, y, q);
                }
                int row = wm * 64 + mi * 16 + 8 * h + g;
                atomicAdd(&red[256 + row], s);
                atomicAdd(&red[384 + row], q);
            }
        }
    }
    __syncthreads();

    if (tid < 128) {
        atomicAdd(&g_colstat[bc * 128 + tid].x, red[tid]);
        atomicAdd(&g_colstat[bc * 128 + tid].y, red[128 + tid]);
    } else if (br != bc) {
        int r = tid - 128;
        atomicAdd(&g_colstat[br * 128 + r].x, red[256 + r]);
        atomicAdd(&g_colstat[br * 128 + r].y, red[384 + r]);
    }
}

// ---------------------------------------------------------------------------
__global__ void stats_fin_kernel() {
    int j = blockIdx.x * blockDim.x + threadIdx.x;
    if (j >= NN) return;
    float2 cs = g_colstat[j];
    double smean = (double)cs.x / (double)NN;
    double var = ((double)cs.y - (double)NN * smean * smean) / (double)(NN - 1);
    g_uA[j] = make_float2((float)smean, (float)(1.0 / (2.0 * var)));
}

// ---------------------------------------------------------------------------
__device__ __forceinline__ float neg_term(int lj, int li, float s, float u, float A) {
    float t = u - s;
    float e = fmaf(t * t, A, s * TEMP_INV);
    return (lj != li) ? __expf(e) : 0.f;
}

__global__ void __launch_bounds__(256) neg_kernel(const int* __restrict__ labels) {
    int i0 = blockIdx.x * 4;
    int li0 = __ldg(&labels[i0]);
    int li1 = __ldg(&labels[i0 + 1]);
    int li2 = __ldg(&labels[i0 + 2]);
    int li3 = __ldg(&labels[i0 + 3]);
    const float4* r0 = (const float4*)(g_sim + (size_t)i0 * NN);
    const float4* r1 = r0 + NN / 4;
    const float4* r2 = r1 + NN / 4;
    const float4* r3 = r2 + NN / 4;
    const int4* lab4 = (const int4*)labels;
    const float4* uA4 = (const float4*)g_uA;

    float acc = 0.f;
    for (int j4 = threadIdx.x; j4 < NN / 4; j4 += 256) {
        int4 L = __ldg(&lab4[j4]);
        float4 ua = __ldg(&uA4[2 * j4]);
        float4 ub = __ldg(&uA4[2 * j4 + 1]);
        float4 v0 = r0[j4];
        float4 v1 = r1[j4];
        float4 v2 = r2[j4];
        float4 v3 = r3[j4];

        acc += neg_term(L.x, li0, v0.x, ua.x, ua.y);
        acc += neg_term(L.y, li0, v0.y, ua.z, ua.w);
        acc += neg_term(L.z, li0, v0.z, ub.x, ub.y);
        acc += neg_term(L.w, li0, v0.w, ub.z, ub.w);

        acc += neg_term(L.x, li1, v1.x, ua.x, ua.y);
        acc += neg_term(L.y, li1, v1.y, ua.z, ua.w);
        acc += neg_term(L.z, li1, v1.z, ub.x, ub.y);
        acc += neg_term(L.w, li1, v1.w, ub.z, ub.w);

        acc += neg_term(L.x, li2, v2.x, ua.x, ua.y);
        acc += neg_term(L.y, li2, v2.y, ua.z, ua.w);
        acc += neg_term(L.z, li2, v2.z, ub.x, ub.y);
        acc += neg_term(L.w, li2, v2.w, ub.z, ub.w);

        acc += neg_term(L.x, li3, v3.x, ua.x, ua.y);
        acc += neg_term(L.y, li3, v3.y, ua.z, ua.w);
        acc += neg_term(L.z, li3, v3.z, ub.x, ub.y);
        acc += neg_term(L.w, li3, v3.w, ub.z, ub.w);
    }

    __shared__ double sh[256];
    int t = threadIdx.x;
    sh[t] = (double)acc;
    __syncthreads();
    for (int st = 128; st > 0; st >>= 1) {
        if (t < st) sh[t] += sh[t + st];
        __syncthreads();
    }
    if (t == 0) atomicAdd(&g_neg, sh[0]);
}

// ---------------------------------------------------------------------------
__global__ void pos_kernel(const int* __restrict__ labels) {
    int i = blockIdx.x * blockDim.x + threadIdx.x;
    double v = 0.0;
    const int b = NN / 2;
    if (i < b && labels[i] == labels[i + b]) {
        float s = g_sim[(size_t)i * NN + (i + b)];
        v = (double)expf(s * TEMP_INV);
    }
    __shared__ double sh[256];
    int t = threadIdx.x;
    sh[t] = v;
    __syncthreads();
    for (int st = 128; st > 0; st >>= 1) {
        if (t < st) sh[t] += sh[t + st];
        __syncthreads();
    }
    if (t == 0) atomicAdd(&g_pos, sh[0]);
}

// ---------------------------------------------------------------------------
__global__ void finalize_kernel(float* out) {
    out[0] = (float)(-log(g_pos / (g_pos + g_neg)));
}

// ---------------------------------------------------------------------------
extern "C" void kernel_launch(void* const* d_in, const int* in_sizes, int n_in,
                              void* d_out, int out_size) {
    const float* z      = (const float*)d_in[0];
    const int*   labels = (const int*)d_in[1];
    float*       out    = (float*)d_out;

    cudaFuncSetAttribute(gemm_kernel, cudaFuncAttributeMaxDynamicSharedMemorySize, GEMM_SMEM);

    init_kernel<<<NN / 256, 256>>>();        // idx 0
    normalize_kernel<<<NN / 8, 256>>>(z);    // idx 1
    nop_kernel<<<1, 1>>>();                  // idx 2 (pads ncu capture to gemm)
    gemm_kernel<<<2080, 256, GEMM_SMEM>>>(); // idx 3  (64*65/2 triangular blocks)
    stats_fin_kernel<<<NN / 256, 256>>>();   // idx 4
    neg_kernel<<<NN / 4, 256>>>(labels);     // idx 5
    pos_kernel<<<(NN / 2 + 255) / 256, 256>>>(labels);
    finalize_kernel<<<1, 1>>>(out);
}

// round 11
// speedup vs baseline: 4.1639x; 1.0186x over previous
#include <cuda_runtime.h>
#include <math.h>
#include <stdint.h>

#define NN 8192
#define DD 512
#define TEMP_INV 5.0f

// Scratch (device globals: no allocation allowed)
__device__ float  g_zn[(size_t)NN * DD];          // 16 MB normalized rows (tf32-rounded)
__device__ float  g_sim[(size_t)NN * NN];         // 256 MB Gram matrix
__device__ float2 g_colstat[NN];                  // per-column {sum, sumsq} of sim
__device__ float2 g_uA[NN];                       // {mean_sim_j, 1/(2*var_j)}
__device__ double g_neg;
__device__ double g_pos;

// ---------------------------------------------------------------------------
__global__ void init_kernel() {
    int j = blockIdx.x * blockDim.x + threadIdx.x;
    if (j < NN) g_colstat[j] = make_float2(0.f, 0.f);
    if (j == 0) { g_neg = 0.0; g_pos = 0.0; }
}

__global__ void nop_kernel() {}   // pads launch index so ncu (idx 3) captures the GEMM

__device__ __forceinline__ float tf32_rna(float x) {
    uint32_t u;
    asm("cvt.rna.tf32.f32 %0, %1;" : "=r"(u) : "f"(x));
    return __uint_as_float(u);
}

// ---------------------------------------------------------------------------
__global__ void normalize_kernel(const float* __restrict__ z) {
    int warp = (blockIdx.x * blockDim.x + threadIdx.x) >> 5;
    int lane = threadIdx.x & 31;
    if (warp >= NN) return;
    const float4* zr = (const float4*)(z + (size_t)warp * DD);
    float4 v[4];
    float ss = 0.f;
#pragma unroll
    for (int t = 0; t < 4; t++) {
        v[t] = zr[lane + 32 * t];
        ss += v[t].x * v[t].x + v[t].y * v[t].y + v[t].z * v[t].z + v[t].w * v[t].w;
    }
#pragma unroll
    for (int o = 16; o > 0; o >>= 1) ss += __shfl_xor_sync(0xffffffffu, ss, o);
    float inv = 1.0f / fmaxf(sqrtf(ss), 1e-12f);
    float4* outp = (float4*)(g_zn + (size_t)warp * DD);
#pragma unroll
    for (int t = 0; t < 4; t++) {
        float4 o4 = make_float4(tf32_rna(v[t].x * inv), tf32_rna(v[t].y * inv),
                                tf32_rna(v[t].z * inv), tf32_rna(v[t].w * inv));
        outp[lane + 32 * t] = o4;
    }
}

// ---------------------------------------------------------------------------
// TF32 mma.sync GEMM, 3-stage cp.async pipeline, smem-transposed epilogue.
// Block 128x128, BK=32, 256 threads (8 warps 2x4), warp tile 64x32.
#define SPITCH 36
#define STAGE_BYTES 36864     // 128*36*4 per matrix; A then B
#define GEMM_SMEM (3 * STAGE_BYTES)
#define TP 132                // epilogue tile pitch (words)

__device__ __forceinline__ void mma_tf32(float c[4], uint32_t a0, uint32_t a1,
                                         uint32_t a2, uint32_t a3,
                                         uint32_t b0, uint32_t b1) {
    asm volatile(
        "mma.sync.aligned.m16n8k8.row.col.f32.tf32.tf32.f32 "
        "{%0,%1,%2,%3}, {%4,%5,%6,%7}, {%8,%9}, {%0,%1,%2,%3};"
        : "+f"(c[0]), "+f"(c[1]), "+f"(c[2]), "+f"(c[3])
        : "r"(a0), "r"(a1), "r"(a2), "r"(a3), "r"(b0), "r"(b1));
}

__device__ __forceinline__ uint32_t smem_u32(const void* p) {
    uint32_t a;
    asm("{ .reg .u64 t; cvta.to.shared.u64 t, %1; cvt.u32.u64 %0, t; }" : "=r"(a) : "l"(p));
    return a;
}

__device__ __forceinline__ void stage_chunk_async(uint32_t sb, int buf, int br, int bc, int chunk) {
    uint32_t bA = sb + buf * STAGE_BYTES;
    uint32_t bB = bA + 18432;
    int t = threadIdx.x;
#pragma unroll
    for (int i = 0; i < 4; i++) {
        int idx = t + 256 * i;            // 0..1023
        int row = idx >> 3, q = idx & 7;
        uint32_t off = (uint32_t)(row * 144 + q * 16);   // 144 = SPITCH*4
        const float* ga = &g_zn[(size_t)(br * 128 + row) * DD + chunk * 32 + q * 4];
        const float* gb = &g_zn[(size_t)(bc * 128 + row) * DD + chunk * 32 + q * 4];
        asm volatile("cp.async.ca.shared.global [%0], [%1], 16;" :: "r"(bA + off), "l"(ga));
        asm volatile("cp.async.ca.shared.global [%0], [%1], 16;" :: "r"(bB + off), "l"(gb));
    }
}

__global__ void __launch_bounds__(256, 2) gemm_kernel() {
    // triangular block index -> (br, bc), br <= bc
    int lin = blockIdx.x;
    int br = (int)(64.5 - sqrt(64.5 * 64.5 - 2.0 * (double)lin));
    while (br * 64 - br * (br - 1) / 2 > lin) br--;
    while ((br + 1) * 64 - (br + 1) * br / 2 <= lin) br++;
    int bc = br + lin - (br * 64 - br * (br - 1) / 2);

    extern __shared__ char smem[];
    uint32_t sb = smem_u32(smem);

    int tid = threadIdx.x;
    int wid = tid >> 5, lane = tid & 31;
    int wm = wid >> 2, wn = wid & 3;
    int g = lane >> 2, c = lane & 3;

    float acc[4][4][4];
#pragma unroll
    for (int i = 0; i < 4; i++)
#pragma unroll
        for (int j = 0; j < 4; j++)
#pragma unroll
            for (int r = 0; r < 4; r++) acc[i][j][r] = 0.f;

    stage_chunk_async(sb, 0, br, bc, 0);
    asm volatile("cp.async.commit_group;");
    stage_chunk_async(sb, 1, br, bc, 1);
    asm volatile("cp.async.commit_group;");

    for (int ck = 0; ck < 16; ck++) {
        int buf = ck % 3;
        asm volatile("cp.async.wait_group 1;");
        __syncthreads();

        const float* fA = (const float*)(smem + buf * STAGE_BYTES) + (wm * 64 + g) * SPITCH;
        const float* fB = (const float*)(smem + buf * STAGE_BYTES + 18432) + (wn * 32 + g) * SPITCH;
#pragma unroll
        for (int ks = 0; ks < 4; ks++) {
            int k0 = ks * 8 + c;
            uint32_t bf[4][2];
#pragma unroll
            for (int nj = 0; nj < 4; nj++) {
                bf[nj][0] = __float_as_uint(fB[nj * 8 * SPITCH + k0]);
                bf[nj][1] = __float_as_uint(fB[nj * 8 * SPITCH + k0 + 4]);
            }
#pragma unroll
            for (int mi = 0; mi < 4; mi++) {
                uint32_t a0 = __float_as_uint(fA[mi * 16 * SPITCH + k0]);
                uint32_t a1 = __float_as_uint(fA[(mi * 16 + 8) * SPITCH + k0]);
                uint32_t a2 = __float_as_uint(fA[mi * 16 * SPITCH + k0 + 4]);
                uint32_t a3 = __float_as_uint(fA[(mi * 16 + 8) * SPITCH + k0 + 4]);
#pragma unroll
                for (int nj = 0; nj < 4; nj++)
                    mma_tf32(acc[mi][nj], a0, a1, a2, a3, bf[nj][0], bf[nj][1]);
            }
        }
        // stage ck+2 into buffer (ck+2)%3 (not read by anyone this iter or next)
        if (ck + 2 < 16) stage_chunk_async(sb, (ck + 2) % 3, br, bc, ck + 2);
        asm volatile("cp.async.commit_group;");   // empty group when no stage: keeps counts
    }
    asm volatile("cp.async.wait_group 0;");
    __syncthreads();   // staging buffers now free for epilogue reuse

    // ================= epilogue through smem =================
    float* tile = (float*)smem;                       // [128][TP]
    float* red  = (float*)(smem + 128 * TP * 4);      // [4][128] (fits in stage area)

    for (int t = tid; t < 512; t += 256) red[t] = 0.f;

    // acc -> tile (STS.64), plus register-based stats into red[]
    {
        int Rl = wm * 64 + g;
        int Cl = wn * 32 + 2 * c;
#pragma unroll
        for (int mi = 0; mi < 4; mi++) {
#pragma unroll
            for (int nj = 0; nj < 4; nj++) {
                int R0 = Rl + mi * 16, R1 = R0 + 8;
                int C = Cl + nj * 8;
                *(float2*)&tile[R0 * TP + C] = make_float2(acc[mi][nj][0], acc[mi][nj][1]);
                *(float2*)&tile[R1 * TP + C] = make_float2(acc[mi][nj][2], acc[mi][nj][3]);
            }
        }
    }
#pragma unroll
    for (int nj = 0; nj < 4; nj++) {
#pragma unroll
        for (int r2 = 0; r2 < 2; r2++) {
            float s = 0.f, q = 0.f;
#pragma unroll
            for (int mi = 0; mi < 4; mi++) {
                float x = acc[mi][nj][r2];     s += x; q = fmaf(x, x, q);
                float y = acc[mi][nj][r2 + 2]; s += y; q = fmaf(y, y, q);
            }
            int col = wn * 32 + nj * 8 + 2 * c + r2;
            atomicAdd(&red[col], s);
            atomicAdd(&red[128 + col], q);
        }
    }
    if (br != bc) {
#pragma unroll
        for (int mi = 0; mi < 4; mi++) {
#pragma unroll
            for (int h = 0; h < 2; h++) {
                float s = 0.f, q = 0.f;
#pragma unroll
                for (int nj = 0; nj < 4; nj++) {
                    float x = acc[mi][nj][2 * h];     s += x; q = fmaf(x, x, q);
                    float y = acc[mi][nj][2 * h + 1]; s += y; q = fmaf(y, y, q);
                }
                int row = wm * 64 + mi * 16 + 8 * h + g;
                atomicAdd(&red[256 + row], s);
                atomicAdd(&red[384 + row], q);
            }
        }
    }
    __syncthreads();

    // direct stores: warp wid owns rows wid*16..wid*16+15; LDS.128 + STG.128 coalesced
#pragma unroll
    for (int rr = 0; rr < 16; rr++) {
        int row = wid * 16 + rr;
        float4 v = *(float4*)&tile[row * TP + 4 * lane];
        *(float4*)&g_sim[(size_t)(br * 128 + row) * NN + bc * 128 + 4 * lane] = v;
    }
    // mirror stores: warp wid owns cols wid*16..+15; lane l reads rows l+32s
    if (br != bc) {
#pragma unroll
        for (int jj = 0; jj < 16; jj++) {
            int j = wid * 16 + jj;
            float* mrow = &g_sim[(size_t)(bc * 128 + j) * NN + br * 128];
#pragma unroll
            for (int s = 0; s < 4; s++) {
                int i = lane + 32 * s;
                mrow[i] = tile[i * TP + j];
            }
        }
    }
    // red -> global column stats
    if (tid < 128) {
        atomicAdd(&g_colstat[bc * 128 + tid].x, red[tid]);
        atomicAdd(&g_colstat[bc * 128 + tid].y, red[128 + tid]);
    } else if (br != bc) {
        int r = tid - 128;
        atomicAdd(&g_colstat[br * 128 + r].x, red[256 + r]);
        atomicAdd(&g_colstat[br * 128 + r].y, red[384 + r]);
    }
}

// ---------------------------------------------------------------------------
__global__ void stats_fin_kernel() {
    int j = blockIdx.x * blockDim.x + threadIdx.x;
    if (j >= NN) return;
    float2 cs = g_colstat[j];
    double smean = (double)cs.x / (double)NN;
    double var = ((double)cs.y - (double)NN * smean * smean) / (double)(NN - 1);
    g_uA[j] = make_float2((float)smean, (float)(1.0 / (2.0 * var)));
}

// ---------------------------------------------------------------------------
__device__ __forceinline__ float neg_term(int lj, int li, float s, float u, float A) {
    float t = u - s;
    float e = fmaf(t * t, A, s * TEMP_INV);
    return (lj != li) ? __expf(e) : 0.f;
}

__global__ void __launch_bounds__(256) neg_kernel(const int* __restrict__ labels) {
    int i0 = blockIdx.x * 4;
    int li0 = __ldg(&labels[i0]);
    int li1 = __ldg(&labels[i0 + 1]);
    int li2 = __ldg(&labels[i0 + 2]);
    int li3 = __ldg(&labels[i0 + 3]);
    const float4* r0 = (const float4*)(g_sim + (size_t)i0 * NN);
    const float4* r1 = r0 + NN / 4;
    const float4* r2 = r1 + NN / 4;
    const float4* r3 = r2 + NN / 4;
    const int4* lab4 = (const int4*)labels;
    const float4* uA4 = (const float4*)g_uA;

    float acc = 0.f;
    for (int j4 = threadIdx.x; j4 < NN / 4; j4 += 256) {
        int4 L = __ldg(&lab4[j4]);
        float4 ua = __ldg(&uA4[2 * j4]);
        float4 ub = __ldg(&uA4[2 * j4 + 1]);
        float4 v0 = r0[j4];
        float4 v1 = r1[j4];
        float4 v2 = r2[j4];
        float4 v3 = r3[j4];

        acc += neg_term(L.x, li0, v0.x, ua.x, ua.y);
        acc += neg_term(L.y, li0, v0.y, ua.z, ua.w);
        acc += neg_term(L.z, li0, v0.z, ub.x, ub.y);
        acc += neg_term(L.w, li0, v0.w, ub.z, ub.w);

        acc += neg_term(L.x, li1, v1.x, ua.x, ua.y);
        acc += neg_term(L.y, li1, v1.y, ua.z, ua.w);
        acc += neg_term(L.z, li1, v1.z, ub.x, ub.y);
        acc += neg_term(L.w, li1, v1.w, ub.z, ub.w);

        acc += neg_term(L.x, li2, v2.x, ua.x, ua.y);
        acc += neg_term(L.y, li2, v2.y, ua.z, ua.w);
        acc += neg_term(L.z, li2, v2.z, ub.x, ub.y);
        acc += neg_term(L.w, li2, v2.w, ub.z, ub.w);

        acc += neg_term(L.x, li3, v3.x, ua.x, ua.y);
        acc += neg_term(L.y, li3, v3.y, ua.z, ua.w);
        acc += neg_term(L.z, li3, v3.z, ub.x, ub.y);
        acc += neg_term(L.w, li3, v3.w, ub.z, ub.w);
    }

    __shared__ double sh[256];
    int t = threadIdx.x;
    sh[t] = (double)acc;
    __syncthreads();
    for (int st = 128; st > 0; st >>= 1) {
        if (t < st) sh[t] += sh[t + st];
        __syncthreads();
    }
    if (t == 0) atomicAdd(&g_neg, sh[0]);
}

// ---------------------------------------------------------------------------
__global__ void pos_kernel(const int* __restrict__ labels) {
    int i = blockIdx.x * blockDim.x + threadIdx.x;
    double v = 0.0;
    const int b = NN / 2;
    if (i < b && labels[i] == labels[i + b]) {
        float s = g_sim[(size_t)i * NN + (i + b)];
        v = (double)expf(s * TEMP_INV);
    }
    __shared__ double sh[256];
    int t = threadIdx.x;
    sh[t] = v;
    __syncthreads();
    for (int st = 128; st > 0; st >>= 1) {
        if (t < st) sh[t] += sh[t + st];
        __syncthreads();
    }
    if (t == 0) atomicAdd(&g_pos, sh[0]);
}

// ---------------------------------------------------------------------------
__global__ void finalize_kernel(float* out) {
    out[0] = (float)(-log(g_pos / (g_pos + g_neg)));
}

// ---------------------------------------------------------------------------
extern "C" void kernel_launch(void* const* d_in, const int* in_sizes, int n_in,
                              void* d_out, int out_size) {
    const float* z      = (const float*)d_in[0];
    const int*   labels = (const int*)d_in[1];
    float*       out    = (float*)d_out;

    cudaFuncSetAttribute(gemm_kernel, cudaFuncAttributeMaxDynamicSharedMemorySize, GEMM_SMEM);

    init_kernel<<<NN / 256, 256>>>();        // idx 0
    normalize_kernel<<<NN / 8, 256>>>(z);    // idx 1
    nop_kernel<<<1, 1>>>();                  // idx 2
    gemm_kernel<<<2080, 256, GEMM_SMEM>>>(); // idx 3 (ncu capture target)
    stats_fin_kernel<<<NN / 256, 256>>>();   // idx 4
    neg_kernel<<<NN / 4, 256>>>(labels);     // idx 5
    pos_kernel<<<(NN / 2 + 255) / 256, 256>>>(labels);
    finalize_kernel<<<1, 1>>>(out);
}